// round 4
// baseline (speedup 1.0000x reference)
#include <cuda_runtime.h>
#include <math.h>

// Problem constants
#define B_  2
#define S_  2048
#define D_  1024
#define H_  16
#define DH_ 64
#define M_ROWS (B_ * S_)          // 4096

// Scratch (device globals: allocation-free). 16B-aligned for float4 access.
// NOTE: these symbols are ONLY referenced from device code — never passed as
// kernel arguments from host (host-side decay gives the wrong address).
__device__ __align__(16) float g_q[B_ * H_ * S_ * DH_];   // [bh][s][d]
__device__ __align__(16) float g_k[B_ * H_ * S_ * DH_];
__device__ __align__(16) float g_v[B_ * H_ * S_ * DH_];
__device__ __align__(16) float g_z[M_ROWS * D_];          // [b*S+s][h*64+d]

// ---------------------------------------------------------------------------
// SGEMM: C[M x N] = A[M x 1024] @ B[1024 x N], 128x128 tile, 256 threads, 8x8
// MODE 0: plain store to C, A from argument.
// MODE 1: QKV scatter epilogue into g_q/g_k/g_v, A from argument.
// MODE 2: A = g_z (bound in device code), plain store to C.
// ---------------------------------------------------------------------------
template <int N, int MODE>
__global__ __launch_bounds__(256) void sgemm_kernel(const float* __restrict__ A_,
                                                    const float* __restrict__ Bm,
                                                    float* __restrict__ C) {
    const float* A = (MODE == 2) ? (const float*)g_z : A_;

    __shared__ __align__(16) float As[8][128];
    __shared__ __align__(16) float Bs[8][128];

    const int tid = threadIdx.x;
    const int tx = tid & 15;           // 0..15
    const int ty = tid >> 4;           // 0..15
    const int m0 = blockIdx.y * 128;
    const int n0 = blockIdx.x * 128;

    const int arow = tid >> 1;         // 0..127
    const int acol = (tid & 1) * 4;    // 0 or 4
    const int brow = tid >> 5;         // 0..7
    const int bcol = (tid & 31) * 4;   // 0..124

    const float* Ap = A + (size_t)(m0 + arow) * 1024 + acol;
    const float* Bp = Bm + (size_t)brow * N + n0 + bcol;

    float acc[8][8];
#pragma unroll
    for (int i = 0; i < 8; i++)
#pragma unroll
        for (int j = 0; j < 8; j++) acc[i][j] = 0.f;

    for (int k0 = 0; k0 < 1024; k0 += 8) {
        float4 av = *(const float4*)(Ap + k0);
        float4 bv = *(const float4*)(Bp + (size_t)k0 * N);
        __syncthreads();
        As[acol + 0][arow] = av.x;
        As[acol + 1][arow] = av.y;
        As[acol + 2][arow] = av.z;
        As[acol + 3][arow] = av.w;
        *(float4*)&Bs[brow][bcol] = bv;
        __syncthreads();

#pragma unroll
        for (int kk = 0; kk < 8; kk++) {
            float a[8], b[8];
            *(float4*)(a)     = *(float4*)&As[kk][ty * 8];
            *(float4*)(a + 4) = *(float4*)&As[kk][ty * 8 + 4];
            *(float4*)(b)     = *(float4*)&Bs[kk][tx * 8];
            *(float4*)(b + 4) = *(float4*)&Bs[kk][tx * 8 + 4];
#pragma unroll
            for (int i = 0; i < 8; i++)
#pragma unroll
                for (int j = 0; j < 8; j++) acc[i][j] = fmaf(a[i], b[j], acc[i][j]);
        }
    }

#pragma unroll
    for (int i = 0; i < 8; i++) {
        const int m = m0 + ty * 8 + i;
        const int bb = m >> 11;        // batch
        const int s  = m & 2047;       // seq pos
#pragma unroll
        for (int j = 0; j < 8; j++) {
            const int e = n0 + tx * 8 + j;
            if (MODE == 1) {
                const int c   = e >> 10;        // 0=q,1=k,2=v
                const int rem = e & 1023;
                const int h   = rem >> 6;
                const int d   = rem & 63;
                float* dst = (c == 0) ? g_q : (c == 1) ? g_k : g_v;
                dst[(size_t)(((bb << 4) + h) * S_ + s) * DH_ + d] = acc[i][j];
            } else {
                C[(size_t)m * N + e] = acc[i][j];
            }
        }
    }
}

// ---------------------------------------------------------------------------
// RoPE in place on g_q AND g_k (selected by index range; no symbol args).
// Layout [bh][s][dh]. One launch covers both arrays.
// ---------------------------------------------------------------------------
__global__ void rope_kernel() {
    const int total = B_ * H_ * S_ * (DH_ / 2);   // per array
    int idx = blockIdx.x * blockDim.x + threadIdx.x;
    float* p = g_q;
    if (idx >= total) { p = g_k; idx -= total; }

    const int i = idx & 31;               // freq index 0..31
    const int s = (idx >> 5) & (S_ - 1);  // seq pos
    const int base = (idx >> 5) << 6;     // row start

    const float invf = (float)exp(-log(10000.0) * (double)i / 32.0);
    const float ang = (float)s * invf;
    const float c = cosf(ang);
    const float sn = sinf(ang);

    const float u1 = p[base + i];
    const float u2 = p[base + 32 + i];
    p[base + i]      = u1 * c - u2 * sn;
    p[base + 32 + i] = u2 * c + u1 * sn;
}

// ---------------------------------------------------------------------------
// Causal flash attention, fp32. 64x64 tiles, 256 threads, 4x4 microtiles.
// grid: (S/64 = 32 query tiles, B*H = 32). Globals referenced device-side.
// Output into g_z with layout [b*S+s][h*64+d].
// ---------------------------------------------------------------------------
__global__ __launch_bounds__(256) void attn_kernel() {
    __shared__ __align__(16) float qT[64][64];   // [d][row]
    __shared__ __align__(16) float kT[64][64];   // [d][col]; reused as pT[col][row]
    __shared__ __align__(16) float vs[64][64];   // [col][d]

    const int tid = threadIdx.x;
    const int tx = tid & 15;
    const int ty = tid >> 4;
    const int qt = blockIdx.x;
    const int bh = blockIdx.y;

    const float* Q = g_q + (size_t)bh * S_ * DH_;
    const float* K = g_k + (size_t)bh * S_ * DH_;
    const float* V = g_v + (size_t)bh * S_ * DH_;

    const int r  = tid >> 2;          // 0..63 row for tile loads
    const int d0 = (tid & 3) * 16;    // 0,16,32,48

    // Load Q tile transposed
#pragma unroll
    for (int i = 0; i < 4; i++) {
        float4 v4 = *(const float4*)(Q + (size_t)(qt * 64 + r) * DH_ + d0 + i * 4);
        qT[d0 + i * 4 + 0][r] = v4.x;
        qT[d0 + i * 4 + 1][r] = v4.y;
        qT[d0 + i * 4 + 2][r] = v4.z;
        qT[d0 + i * 4 + 3][r] = v4.w;
    }

    float o[4][4];
    float mrow[4], lrow[4];
#pragma unroll
    for (int i = 0; i < 4; i++) {
        mrow[i] = -1e30f;
        lrow[i] = 0.f;
#pragma unroll
        for (int j = 0; j < 4; j++) o[i][j] = 0.f;
    }

    for (int kt = 0; kt <= qt; kt++) {
        __syncthreads();  // protect kT/vs from previous iteration readers (fences qT on iter 0)
        // Load K transposed + V natural
#pragma unroll
        for (int i = 0; i < 4; i++) {
            float4 v4 = *(const float4*)(K + (size_t)(kt * 64 + r) * DH_ + d0 + i * 4);
            kT[d0 + i * 4 + 0][r] = v4.x;
            kT[d0 + i * 4 + 1][r] = v4.y;
            kT[d0 + i * 4 + 2][r] = v4.z;
            kT[d0 + i * 4 + 3][r] = v4.w;
            *(float4*)&vs[r][d0 + i * 4] =
                *(const float4*)(V + (size_t)(kt * 64 + r) * DH_ + d0 + i * 4);
        }
        __syncthreads();

        // S = (Q K^T) * scale
        float s[4][4];
#pragma unroll
        for (int i = 0; i < 4; i++)
#pragma unroll
            for (int j = 0; j < 4; j++) s[i][j] = 0.f;
        for (int d = 0; d < 64; d++) {
            float4 a = *(float4*)&qT[d][ty * 4];
            float4 b = *(float4*)&kT[d][tx * 4];
            float av[4] = {a.x, a.y, a.z, a.w};
            float bv[4] = {b.x, b.y, b.z, b.w};
#pragma unroll
            for (int i = 0; i < 4; i++)
#pragma unroll
                for (int j = 0; j < 4; j++) s[i][j] = fmaf(av[i], bv[j], s[i][j]);
        }
#pragma unroll
        for (int i = 0; i < 4; i++)
#pragma unroll
            for (int j = 0; j < 4; j++) {
                s[i][j] *= 0.125f;
                if (kt == qt && (tx * 4 + j) > (ty * 4 + i)) s[i][j] = -1e30f;
            }

        // Row max over the 16 tx-lanes (half-warp shuffle groups)
        float tm[4];
#pragma unroll
        for (int i = 0; i < 4; i++) {
            tm[i] = fmaxf(fmaxf(s[i][0], s[i][1]), fmaxf(s[i][2], s[i][3]));
        }
#pragma unroll
        for (int off = 1; off < 16; off <<= 1)
#pragma unroll
            for (int i = 0; i < 4; i++)
                tm[i] = fmaxf(tm[i], __shfl_xor_sync(0xffffffffu, tm[i], off));

        float corr[4];
#pragma unroll
        for (int i = 0; i < 4; i++) {
            float mnew = fmaxf(mrow[i], tm[i]);
            corr[i] = expf(mrow[i] - mnew);
            mrow[i] = mnew;
        }

        float p[4][4], ts[4];
#pragma unroll
        for (int i = 0; i < 4; i++) {
            ts[i] = 0.f;
#pragma unroll
            for (int j = 0; j < 4; j++) {
                p[i][j] = expf(s[i][j] - mrow[i]);
                ts[i] += p[i][j];
            }
        }
#pragma unroll
        for (int off = 1; off < 16; off <<= 1)
#pragma unroll
            for (int i = 0; i < 4; i++)
                ts[i] += __shfl_xor_sync(0xffffffffu, ts[i], off);

#pragma unroll
        for (int i = 0; i < 4; i++) {
            lrow[i] = lrow[i] * corr[i] + ts[i];
#pragma unroll
            for (int j = 0; j < 4; j++) o[i][j] *= corr[i];
        }

        // Stash P into kT (as pT[col][row]) after everyone is done reading kT
        __syncthreads();
#pragma unroll
        for (int i = 0; i < 4; i++)
#pragma unroll
            for (int j = 0; j < 4; j++) kT[tx * 4 + j][ty * 4 + i] = p[i][j];
        __syncthreads();

        // O += P @ V
        for (int c = 0; c < 64; c++) {
            float4 a = *(float4*)&kT[c][ty * 4];
            float4 b = *(float4*)&vs[c][tx * 4];
            float av[4] = {a.x, a.y, a.z, a.w};
            float bv[4] = {b.x, b.y, b.z, b.w};
#pragma unroll
            for (int i = 0; i < 4; i++)
#pragma unroll
                for (int j = 0; j < 4; j++) o[i][j] = fmaf(av[i], bv[j], o[i][j]);
        }
    }

    // Finalize and write z[b][s][h*64+d]
    const int bb = bh >> 4;
    const int h  = bh & 15;
#pragma unroll
    for (int i = 0; i < 4; i++) {
        const float inv = 1.f / lrow[i];
        const int srow = qt * 64 + ty * 4 + i;
#pragma unroll
        for (int j = 0; j < 4; j++) {
            g_z[(size_t)(bb * S_ + srow) * D_ + h * DH_ + tx * 4 + j] = o[i][j] * inv;
        }
    }
}

// ---------------------------------------------------------------------------
extern "C" void kernel_launch(void* const* d_in, const int* in_sizes, int n_in,
                              void* d_out, int out_size) {
    // Robust input resolution (element or byte counts; fallback positional).
    const float* x = nullptr;
    const float* W_qkv = nullptr;
    const float* W_o = nullptr;

    bool elem_mode = false, byte_mode = false;
    for (int i = 0; i < n_in; i++) {
        if (in_sizes[i] == 3145728)  elem_mode = true;   // W_qkv elems
        if (in_sizes[i] == 12582912) byte_mode = true;   // W_qkv bytes
    }
    if (elem_mode) {
        for (int i = 0; i < n_in; i++) {
            if (in_sizes[i] == 4194304)      x     = (const float*)d_in[i];
            else if (in_sizes[i] == 3145728) W_qkv = (const float*)d_in[i];
            else if (in_sizes[i] == 1048576) W_o   = (const float*)d_in[i];
        }
    } else if (byte_mode) {
        for (int i = 0; i < n_in; i++) {
            if (in_sizes[i] == 16777216)      x     = (const float*)d_in[i];
            else if (in_sizes[i] == 12582912) W_qkv = (const float*)d_in[i];
            else if (in_sizes[i] == 4194304)  W_o   = (const float*)d_in[i];
        }
    }
    if (!x || !W_qkv || !W_o) {       // positional fallback (x, W_qkv, W_o)
        x     = (const float*)d_in[0];
        W_qkv = (const float*)d_in[1];
        W_o   = (const float*)d_in[2];
    }
    float* out = (float*)d_out;       // [2,2048,1024]

    // 1) QKV projection, scatter into g_q/g_k/g_v (device-side symbol refs)
    sgemm_kernel<3072, 1><<<dim3(3072 / 128, M_ROWS / 128), 256>>>(x, W_qkv, nullptr);

    // 2) RoPE on q and k (one launch, arrays selected device-side)
    const int rope_threads = 2 * B_ * H_ * S_ * (DH_ / 2);
    rope_kernel<<<rope_threads / 256, 256>>>();

    // 3) Causal flash attention -> g_z
    attn_kernel<<<dim3(S_ / 64, B_ * H_), 256>>>();

    // 4) Output projection: A bound to g_z inside the kernel (MODE=2)
    sgemm_kernel<1024, 2><<<dim3(1024 / 128, M_ROWS / 128), 256>>>(nullptr, W_o, out);
}

// round 8
// speedup vs baseline: 1.4458x; 1.4458x over previous
#include <cuda_runtime.h>
#include <cuda_bf16.h>
#include <stdint.h>
#include <math.h>

// Problem constants
#define B_  2
#define S_  2048
#define D_  1024
#define H_  16
#define DH_ 64
#define M_ROWS (B_ * S_)

// ---------------------------------------------------------------------------
// Device-global scratch (allocation-free). Referenced ONLY from device code.
// ---------------------------------------------------------------------------
__device__ __align__(16) float g_q[B_ * H_ * S_ * DH_];
__device__ __align__(16) float g_k[B_ * H_ * S_ * DH_];
__device__ __align__(16) float g_v[B_ * H_ * S_ * DH_];
__device__ __align__(16) float g_z[M_ROWS * D_];

__device__ __align__(16) __nv_bfloat16 g_xhi[M_ROWS * D_];
__device__ __align__(16) __nv_bfloat16 g_xlo[M_ROWS * D_];
__device__ __align__(16) __nv_bfloat16 g_wqhi[D_ * 3 * D_];
__device__ __align__(16) __nv_bfloat16 g_wqlo[D_ * 3 * D_];
__device__ __align__(16) __nv_bfloat16 g_wohi[D_ * D_];
__device__ __align__(16) __nv_bfloat16 g_wolo[D_ * D_];
__device__ __align__(16) __nv_bfloat16 g_zhi[M_ROWS * D_];
__device__ __align__(16) __nv_bfloat16 g_zlo[M_ROWS * D_];

// ---------------------------------------------------------------------------
// RoPE in place on g_q AND g_k (selected by index range). Layout [bh][s][dh].
// ---------------------------------------------------------------------------
__global__ void rope_kernel() {
    const int total = B_ * H_ * S_ * (DH_ / 2);
    int idx = blockIdx.x * blockDim.x + threadIdx.x;
    float* p;
    if (idx >= total) {
        p = &g_k[0];
        idx -= total;
    } else {
        p = &g_q[0];
    }

    const int i = idx & 31;
    const int s = (idx >> 5) & (S_ - 1);
    const int base = (idx >> 5) << 6;

    const float invf = (float)exp(-log(10000.0) * (double)i / 32.0);
    const float ang = (float)s * invf;
    const float cv = cosf(ang);
    const float sv = sinf(ang);

    const float u1 = p[base + i];
    const float u2 = p[base + 32 + i];
    p[base + i]      = u1 * cv - u2 * sv;
    p[base + 32 + i] = u2 * cv + u1 * sv;
}

// ---------------------------------------------------------------------------
// Causal flash attention, fp32. 64x64 tiles, 256 threads, 4x4 microtiles.
// grid: (32 query tiles, 32 bh). Output g_z[b*S+s][h*64+d].
// (Verbatim from the round-4 passing kernel.)
// ---------------------------------------------------------------------------
__global__ __launch_bounds__(256) void attn_kernel() {
    __shared__ __align__(16) float qT[64][64];
    __shared__ __align__(16) float kT[64][64];
    __shared__ __align__(16) float vs[64][64];

    const int tid = threadIdx.x;
    const int tx = tid & 15;
    const int ty = tid >> 4;
    const int qt = blockIdx.x;
    const int bh = blockIdx.y;

    const float* Q = &g_q[0] + (size_t)bh * S_ * DH_;
    const float* K = &g_k[0] + (size_t)bh * S_ * DH_;
    const float* V = &g_v[0] + (size_t)bh * S_ * DH_;

    const int r  = tid >> 2;
    const int d0 = (tid & 3) * 16;

#pragma unroll
    for (int i = 0; i < 4; i++) {
        float4 v4 = *(const float4*)(Q + (size_t)(qt * 64 + r) * DH_ + d0 + i * 4);
        qT[d0 + i * 4 + 0][r] = v4.x;
        qT[d0 + i * 4 + 1][r] = v4.y;
        qT[d0 + i * 4 + 2][r] = v4.z;
        qT[d0 + i * 4 + 3][r] = v4.w;
    }

    float o[4][4];
    float mrow[4];
    float lrow[4];
#pragma unroll
    for (int i = 0; i < 4; i++) {
        mrow[i] = -1e30f;
        lrow[i] = 0.f;
#pragma unroll
        for (int j = 0; j < 4; j++) {
            o[i][j] = 0.f;
        }
    }

    for (int kt = 0; kt <= qt; kt++) {
        __syncthreads();
#pragma unroll
        for (int i = 0; i < 4; i++) {
            float4 v4 = *(const float4*)(K + (size_t)(kt * 64 + r) * DH_ + d0 + i * 4);
            kT[d0 + i * 4 + 0][r] = v4.x;
            kT[d0 + i * 4 + 1][r] = v4.y;
            kT[d0 + i * 4 + 2][r] = v4.z;
            kT[d0 + i * 4 + 3][r] = v4.w;
            *(float4*)(&vs[r][d0 + i * 4]) =
                *(const float4*)(V + (size_t)(kt * 64 + r) * DH_ + d0 + i * 4);
        }
        __syncthreads();

        float sc[4][4];
#pragma unroll
        for (int i = 0; i < 4; i++) {
#pragma unroll
            for (int j = 0; j < 4; j++) {
                sc[i][j] = 0.f;
            }
        }
        for (int d = 0; d < 64; d++) {
            float4 a = *(float4*)(&qT[d][ty * 4]);
            float4 b = *(float4*)(&kT[d][tx * 4]);
            float av[4];
            float bv[4];
            av[0] = a.x; av[1] = a.y; av[2] = a.z; av[3] = a.w;
            bv[0] = b.x; bv[1] = b.y; bv[2] = b.z; bv[3] = b.w;
#pragma unroll
            for (int i = 0; i < 4; i++) {
#pragma unroll
                for (int j = 0; j < 4; j++) {
                    sc[i][j] = fmaf(av[i], bv[j], sc[i][j]);
                }
            }
        }
#pragma unroll
        for (int i = 0; i < 4; i++) {
#pragma unroll
            for (int j = 0; j < 4; j++) {
                sc[i][j] *= 0.125f;
                if (kt == qt && (tx * 4 + j) > (ty * 4 + i)) {
                    sc[i][j] = -1e30f;
                }
            }
        }

        float tmx[4];
#pragma unroll
        for (int i = 0; i < 4; i++) {
            tmx[i] = fmaxf(fmaxf(sc[i][0], sc[i][1]), fmaxf(sc[i][2], sc[i][3]));
        }
#pragma unroll
        for (int off = 1; off < 16; off <<= 1) {
#pragma unroll
            for (int i = 0; i < 4; i++) {
                tmx[i] = fmaxf(tmx[i], __shfl_xor_sync(0xffffffffu, tmx[i], off));
            }
        }

        float corr[4];
#pragma unroll
        for (int i = 0; i < 4; i++) {
            float mnew = fmaxf(mrow[i], tmx[i]);
            corr[i] = expf(mrow[i] - mnew);
            mrow[i] = mnew;
        }

        float pr[4][4];
        float ts[4];
#pragma unroll
        for (int i = 0; i < 4; i++) {
            ts[i] = 0.f;
#pragma unroll
            for (int j = 0; j < 4; j++) {
                pr[i][j] = expf(sc[i][j] - mrow[i]);
                ts[i] += pr[i][j];
            }
        }
#pragma unroll
        for (int off = 1; off < 16; off <<= 1) {
#pragma unroll
            for (int i = 0; i < 4; i++) {
                ts[i] += __shfl_xor_sync(0xffffffffu, ts[i], off);
            }
        }

#pragma unroll
        for (int i = 0; i < 4; i++) {
            lrow[i] = lrow[i] * corr[i] + ts[i];
#pragma unroll
            for (int j = 0; j < 4; j++) {
                o[i][j] *= corr[i];
            }
        }

        __syncthreads();
#pragma unroll
        for (int i = 0; i < 4; i++) {
#pragma unroll
            for (int j = 0; j < 4; j++) {
                kT[tx * 4 + j][ty * 4 + i] = pr[i][j];
            }
        }
        __syncthreads();

        for (int c = 0; c < 64; c++) {
            float4 a = *(float4*)(&kT[c][ty * 4]);
            float4 b = *(float4*)(&vs[c][tx * 4]);
            float av[4];
            float bv[4];
            av[0] = a.x; av[1] = a.y; av[2] = a.z; av[3] = a.w;
            bv[0] = b.x; bv[1] = b.y; bv[2] = b.z; bv[3] = b.w;
#pragma unroll
            for (int i = 0; i < 4; i++) {
#pragma unroll
                for (int j = 0; j < 4; j++) {
                    o[i][j] = fmaf(av[i], bv[j], o[i][j]);
                }
            }
        }
    }

    const int bb = bh >> 4;
    const int hh = bh & 15;
#pragma unroll
    for (int i = 0; i < 4; i++) {
        const float inv = 1.f / lrow[i];
        const int srow = qt * 64 + ty * 4 + i;
#pragma unroll
        for (int j = 0; j < 4; j++) {
            g_z[(size_t)(bb * S_ + srow) * D_ + hh * DH_ + tx * 4 + j] = o[i][j] * inv;
        }
    }
}

// ===========================================================================
// NEW CODE BELOW (placed last for error-log visibility)
// ===========================================================================

// Split fp32 -> (bf16 hi, bf16 lo). WHICH: 0 = x, 1 = W_qkv, 2 = W_o, 3 = g_z.
template <int WHICH>
__global__ void split_kernel(const float* src, int n) {
    int i = blockIdx.x * blockDim.x + threadIdx.x;
    if (i >= n) return;
    float v;
    if (WHICH == 3) {
        v = g_z[i];
    } else {
        v = src[i];
    }
    __nv_bfloat16 hv = __float2bfloat16(v);
    __nv_bfloat16 lv = __float2bfloat16(v - __bfloat162float(hv));
    if (WHICH == 0) { g_xhi[i] = hv; g_xlo[i] = lv; }
    if (WHICH == 1) { g_wqhi[i] = hv; g_wqlo[i] = lv; }
    if (WHICH == 2) { g_wohi[i] = hv; g_wolo[i] = lv; }
    if (WHICH == 3) { g_zhi[i] = hv; g_zlo[i] = lv; }
}

// PTX helpers. Vector operand lists are written with spaces so the source
// never contains brace-percent sequences that upset text renderers.
__device__ __forceinline__ unsigned int smem_u32(const void* p) {
    unsigned int addr;
    asm("{ .reg .u64 tmp; cvta.to.shared.u64 tmp, %1; cvt.u32.u64 %0, tmp; }"
        : "=r"(addr) : "l"(p));
    return addr;
}

#define LDSM_X4(R0, R1, R2, R3, ADDR)                                         \
    asm volatile(                                                             \
        "ldmatrix.sync.aligned.m8n8.x4.shared.b16 { %0, %1, %2, %3 }, [ %4 ];"\
        : "=r"(R0), "=r"(R1), "=r"(R2), "=r"(R3)                              \
        : "r"(ADDR))

#define LDSM_X2T(R0, R1, ADDR)                                                \
    asm volatile(                                                             \
        "ldmatrix.sync.aligned.m8n8.x2.trans.shared.b16 { %0, %1 }, [ %2 ];"  \
        : "=r"(R0), "=r"(R1)                                                  \
        : "r"(ADDR))

#define MMA16816(C0, C1, C2, C3, A0, A1, A2, A3, B0, B1)                      \
    asm volatile(                                                             \
        "mma.sync.aligned.m16n8k16.row.col.f32.bf16.bf16.f32 "                \
        "{ %0, %1, %2, %3 }, { %4, %5, %6, %7 }, { %8, %9 }, "                \
        "{ %0, %1, %2, %3 };"                                                 \
        : "+f"(C0), "+f"(C1), "+f"(C2), "+f"(C3)                              \
        : "r"(A0), "r"(A1), "r"(A2), "r"(A3), "r"(B0), "r"(B1))

// ---------------------------------------------------------------------------
// Split-bf16 tensor-core GEMM: C[4096 x N] = A[4096 x 1024] @ B[1024 x N].
// 3 passes: hi*hi + hi*lo + lo*hi, fp32 accumulate (~fp32 accuracy).
// Block tile 128x128x32, 8 warps, warp tile 64x32 (4x4 m16n8k16 fragments).
// MODE 1: A = x hi/lo, B = W_qkv hi/lo, scatter epilogue into g_q/g_k/g_v.
// MODE 0: A = z hi/lo, B = W_o hi/lo, plain store into C.
// ---------------------------------------------------------------------------
template <int N, int MODE>
__global__ __launch_bounds__(256) void mma_gemm(float* __restrict__ C) {
    const __nv_bfloat16* Ahi;
    const __nv_bfloat16* Alo;
    const __nv_bfloat16* Bhi;
    const __nv_bfloat16* Blo;
    if (MODE == 1) {
        Ahi = &g_xhi[0];
        Alo = &g_xlo[0];
        Bhi = &g_wqhi[0];
        Blo = &g_wqlo[0];
    } else {
        Ahi = &g_zhi[0];
        Alo = &g_zlo[0];
        Bhi = &g_wohi[0];
        Blo = &g_wolo[0];
    }

    __shared__ __align__(16) __nv_bfloat16 Ah[128][40];
    __shared__ __align__(16) __nv_bfloat16 Al[128][40];
    __shared__ __align__(16) __nv_bfloat16 Bh[32][136];
    __shared__ __align__(16) __nv_bfloat16 Bl[32][136];

    const int tid = threadIdx.x;
    const int lane = tid & 31;
    const int wid = tid >> 5;
    const int warp_m = wid >> 2;
    const int warp_n = wid & 3;
    const int m0 = blockIdx.y * 128;
    const int n0 = blockIdx.x * 128;

    float acc[4][4][4];
#pragma unroll
    for (int i = 0; i < 4; i++) {
#pragma unroll
        for (int j = 0; j < 4; j++) {
#pragma unroll
            for (int e = 0; e < 4; e++) {
                acc[i][j][e] = 0.f;
            }
        }
    }

    const int a_r = lane & 15;                     // A frag row within 16
    const int a_c = ((lane & 16) != 0) ? 8 : 0;    // A frag col half
    const int b_r = lane & 15;                     // B frag k row

    for (int k0 = 0; k0 < 1024; k0 += 32) {
        __syncthreads();
#pragma unroll
        for (int i = 0; i < 2; i++) {
            int idx = tid + i * 256;
            int rr = idx >> 2;
            int cc = (idx & 3) * 8;
            *(uint4*)(&Ah[rr][cc]) = *(const uint4*)(&Ahi[(size_t)(m0 + rr) * 1024 + k0 + cc]);
            *(uint4*)(&Al[rr][cc]) = *(const uint4*)(&Alo[(size_t)(m0 + rr) * 1024 + k0 + cc]);
        }
#pragma unroll
        for (int i = 0; i < 2; i++) {
            int idx = tid + i * 256;
            int rr = idx >> 4;
            int cc = (idx & 15) * 8;
            *(uint4*)(&Bh[rr][cc]) = *(const uint4*)(&Bhi[(size_t)(k0 + rr) * N + n0 + cc]);
            *(uint4*)(&Bl[rr][cc]) = *(const uint4*)(&Blo[(size_t)(k0 + rr) * N + n0 + cc]);
        }
        __syncthreads();

#pragma unroll
        for (int ks = 0; ks < 2; ks++) {
            unsigned int bh0[4];
            unsigned int bh1[4];
            unsigned int bl0[4];
            unsigned int bl1[4];
#pragma unroll
            for (int nf = 0; nf < 4; nf++) {
                LDSM_X2T(bh0[nf], bh1[nf],
                         smem_u32(&Bh[ks * 16 + b_r][warp_n * 32 + nf * 8]));
                LDSM_X2T(bl0[nf], bl1[nf],
                         smem_u32(&Bl[ks * 16 + b_r][warp_n * 32 + nf * 8]));
            }
#pragma unroll
            for (int mf = 0; mf < 4; mf++) {
                unsigned int ah0;
                unsigned int ah1;
                unsigned int ah2;
                unsigned int ah3;
                unsigned int al0;
                unsigned int al1;
                unsigned int al2;
                unsigned int al3;
                LDSM_X4(ah0, ah1, ah2, ah3,
                        smem_u32(&Ah[warp_m * 64 + mf * 16 + a_r][ks * 16 + a_c]));
                LDSM_X4(al0, al1, al2, al3,
                        smem_u32(&Al[warp_m * 64 + mf * 16 + a_r][ks * 16 + a_c]));
#pragma unroll
                for (int nf = 0; nf < 4; nf++) {
                    MMA16816(acc[mf][nf][0], acc[mf][nf][1], acc[mf][nf][2], acc[mf][nf][3],
                             ah0, ah1, ah2, ah3, bh0[nf], bh1[nf]);
                    MMA16816(acc[mf][nf][0], acc[mf][nf][1], acc[mf][nf][2], acc[mf][nf][3],
                             ah0, ah1, ah2, ah3, bl0[nf], bl1[nf]);
                    MMA16816(acc[mf][nf][0], acc[mf][nf][1], acc[mf][nf][2], acc[mf][nf][3],
                             al0, al1, al2, al3, bh0[nf], bh1[nf]);
                }
            }
        }
    }

    const int gg = lane >> 2;
    const int t2 = (lane & 3) * 2;
#pragma unroll
    for (int mf = 0; mf < 4; mf++) {
#pragma unroll
        for (int nf = 0; nf < 4; nf++) {
#pragma unroll
            for (int e = 0; e < 4; e++) {
                const int row = warp_m * 64 + mf * 16 + gg + ((e >= 2) ? 8 : 0);
                const int col = warp_n * 32 + nf * 8 + t2 + (e & 1);
                const int m = m0 + row;
                const int ecol = n0 + col;
                const float v = acc[mf][nf][e];
                if (MODE == 1) {
                    const int bb = m >> 11;
                    const int ss = m & 2047;
                    const int c3 = ecol >> 10;
                    const int rem = ecol & 1023;
                    const int hh = rem >> 6;
                    const int dd = rem & 63;
                    float* dst;
                    if (c3 == 0) {
                        dst = &g_q[0];
                    } else if (c3 == 1) {
                        dst = &g_k[0];
                    } else {
                        dst = &g_v[0];
                    }
                    dst[(size_t)(((bb << 4) + hh) * S_ + ss) * DH_ + dd] = v;
                } else {
                    C[(size_t)m * N + ecol] = v;
                }
            }
        }
    }
}

// ---------------------------------------------------------------------------
extern "C" void kernel_launch(void* const* d_in, const int* in_sizes, int n_in,
                              void* d_out, int out_size) {
    const float* x = 0;
    const float* W_qkv = 0;
    const float* W_o = 0;

    bool elem_mode = false;
    bool byte_mode = false;
    for (int i = 0; i < n_in; i++) {
        if (in_sizes[i] == 3145728)  elem_mode = true;
        if (in_sizes[i] == 12582912) byte_mode = true;
    }
    if (elem_mode) {
        for (int i = 0; i < n_in; i++) {
            if (in_sizes[i] == 4194304)      x     = (const float*)d_in[i];
            else if (in_sizes[i] == 3145728) W_qkv = (const float*)d_in[i];
            else if (in_sizes[i] == 1048576) W_o   = (const float*)d_in[i];
        }
    } else if (byte_mode) {
        for (int i = 0; i < n_in; i++) {
            if (in_sizes[i] == 16777216)      x     = (const float*)d_in[i];
            else if (in_sizes[i] == 12582912) W_qkv = (const float*)d_in[i];
            else if (in_sizes[i] == 4194304)  W_o   = (const float*)d_in[i];
        }
    }
    if (x == 0 || W_qkv == 0 || W_o == 0) {
        x     = (const float*)d_in[0];
        W_qkv = (const float*)d_in[1];
        W_o   = (const float*)d_in[2];
    }
    float* out = (float*)d_out;

    // 0) split inputs to bf16 hi/lo
    split_kernel<0><<<(M_ROWS * D_ + 255) / 256, 256>>>(x, M_ROWS * D_);
    split_kernel<1><<<(D_ * 3 * D_ + 255) / 256, 256>>>(W_qkv, D_ * 3 * D_);
    split_kernel<2><<<(D_ * D_ + 255) / 256, 256>>>(W_o, D_ * D_);

    // 1) QKV projection (tensor cores), scatter into g_q/g_k/g_v
    mma_gemm<3072, 1><<<dim3(3072 / 128, M_ROWS / 128), 256>>>(0);

    // 2) RoPE on q and k
    rope_kernel<<<(2 * B_ * H_ * S_ * (DH_ / 2)) / 256, 256>>>();

    // 3) Causal flash attention -> g_z
    attn_kernel<<<dim3(S_ / 64, B_ * H_), 256>>>();

    // 4) split z, then O-projection (tensor cores)
    split_kernel<3><<<(M_ROWS * D_ + 255) / 256, 256>>>(0, M_ROWS * D_);
    mma_gemm<1024, 0><<<dim3(1024 / 128, M_ROWS / 128), 256>>>(out);
}

// round 9
// speedup vs baseline: 2.1492x; 1.4865x over previous
#include <cuda_runtime.h>
#include <cuda_bf16.h>
#include <cuda_fp16.h>
#include <stdint.h>
#include <math.h>

// Problem constants
#define B_  2
#define S_  2048
#define D_  1024
#define H_  16
#define DH_ 64
#define M_ROWS (B_ * S_)

// 0.125 * log2(e): folds the 1/sqrt(64) score scale and the exp->exp2
// conversion into Q at RoPE time.
#define QSCALE 0.18033688011112042f

// ---------------------------------------------------------------------------
// Device-global scratch (allocation-free). Referenced ONLY from device code.
// ---------------------------------------------------------------------------
__device__ __align__(16) float g_q[B_ * H_ * S_ * DH_];   // pre-RoPE fp32
__device__ __align__(16) float g_k[B_ * H_ * S_ * DH_];

__device__ __align__(16) __nv_bfloat16 g_qh[B_ * H_ * S_ * DH_];  // post-RoPE, scaled
__device__ __align__(16) __nv_bfloat16 g_ql[B_ * H_ * S_ * DH_];
__device__ __align__(16) __nv_bfloat16 g_kh[B_ * H_ * S_ * DH_];
__device__ __align__(16) __nv_bfloat16 g_kl[B_ * H_ * S_ * DH_];
__device__ __align__(16) __half        g_vh[B_ * H_ * S_ * DH_];
__device__ __align__(16) __half        g_vl[B_ * H_ * S_ * DH_];

__device__ __align__(16) __nv_bfloat16 g_xhi[M_ROWS * D_];
__device__ __align__(16) __nv_bfloat16 g_xlo[M_ROWS * D_];
__device__ __align__(16) __nv_bfloat16 g_wqhi[D_ * 3 * D_];
__device__ __align__(16) __nv_bfloat16 g_wqlo[D_ * 3 * D_];
__device__ __align__(16) __nv_bfloat16 g_wohi[D_ * D_];
__device__ __align__(16) __nv_bfloat16 g_wolo[D_ * D_];
__device__ __align__(16) __nv_bfloat16 g_zhi[M_ROWS * D_];   // attn output, split
__device__ __align__(16) __nv_bfloat16 g_zlo[M_ROWS * D_];

// ---------------------------------------------------------------------------
// PTX helpers (render-safe operand lists)
// ---------------------------------------------------------------------------
__device__ __forceinline__ unsigned int smem_u32(const void* p) {
    unsigned int addr;
    asm("{ .reg .u64 tmp; cvta.to.shared.u64 tmp, %1; cvt.u32.u64 %0, tmp; }"
        : "=r"(addr) : "l"(p));
    return addr;
}

#define LDSM_X4(R0, R1, R2, R3, ADDR)                                         \
    asm volatile(                                                             \
        "ldmatrix.sync.aligned.m8n8.x4.shared.b16 { %0, %1, %2, %3 }, [ %4 ];"\
        : "=r"(R0), "=r"(R1), "=r"(R2), "=r"(R3)                              \
        : "r"(ADDR))

#define LDSM_X2(R0, R1, ADDR)                                                 \
    asm volatile(                                                             \
        "ldmatrix.sync.aligned.m8n8.x2.shared.b16 { %0, %1 }, [ %2 ];"        \
        : "=r"(R0), "=r"(R1)                                                  \
        : "r"(ADDR))

#define LDSM_X2T(R0, R1, ADDR)                                                \
    asm volatile(                                                             \
        "ldmatrix.sync.aligned.m8n8.x2.trans.shared.b16 { %0, %1 }, [ %2 ];"  \
        : "=r"(R0), "=r"(R1)                                                  \
        : "r"(ADDR))

#define MMA_BF16(C0, C1, C2, C3, A0, A1, A2, A3, B0, B1)                      \
    asm volatile(                                                             \
        "mma.sync.aligned.m16n8k16.row.col.f32.bf16.bf16.f32 "                \
        "{ %0, %1, %2, %3 }, { %4, %5, %6, %7 }, { %8, %9 }, "                \
        "{ %0, %1, %2, %3 };"                                                 \
        : "+f"(C0), "+f"(C1), "+f"(C2), "+f"(C3)                              \
        : "r"(A0), "r"(A1), "r"(A2), "r"(A3), "r"(B0), "r"(B1))

#define MMA_F16(C0, C1, C2, C3, A0, A1, A2, A3, B0, B1)                       \
    asm volatile(                                                             \
        "mma.sync.aligned.m16n8k16.row.col.f32.f16.f16.f32 "                  \
        "{ %0, %1, %2, %3 }, { %4, %5, %6, %7 }, { %8, %9 }, "                \
        "{ %0, %1, %2, %3 };"                                                 \
        : "+f"(C0), "+f"(C1), "+f"(C2), "+f"(C3)                              \
        : "r"(A0), "r"(A1), "r"(A2), "r"(A3), "r"(B0), "r"(B1))

// R = f16x2( lo = exp2(S0), hi = exp2(S1) )
#define EX2F16X2(R, S0, S1)                                                   \
    do {                                                                      \
        unsigned int _t;                                                      \
        asm("cvt.rn.f16x2.f32 %0, %1, %2;" : "=r"(_t) : "f"(S1), "f"(S0));    \
        asm("ex2.approx.f16x2 %0, %1;" : "=r"(R) : "r"(_t));                  \
    } while (0)

// ---------------------------------------------------------------------------
// Split fp32 -> (bf16 hi, bf16 lo). WHICH: 0 = x, 1 = W_qkv, 2 = W_o.
// ---------------------------------------------------------------------------
template <int WHICH>
__global__ void split_kernel(const float* src, int n) {
    int i = blockIdx.x * blockDim.x + threadIdx.x;
    if (i >= n) return;
    float v = src[i];
    __nv_bfloat16 hv = __float2bfloat16(v);
    __nv_bfloat16 lv = __float2bfloat16(v - __bfloat162float(hv));
    if (WHICH == 0) { g_xhi[i] = hv; g_xlo[i] = lv; }
    if (WHICH == 1) { g_wqhi[i] = hv; g_wqlo[i] = lv; }
    if (WHICH == 2) { g_wohi[i] = hv; g_wolo[i] = lv; }
}

// ---------------------------------------------------------------------------
// Split-bf16 tensor-core GEMM (validated in round 8).
// MODE 1: A = x hi/lo, B = W_qkv hi/lo; epilogue: q,k -> fp32; v -> f16 hi/lo.
// MODE 0: A = z hi/lo, B = W_o hi/lo, plain store into C.
// ---------------------------------------------------------------------------
template <int N, int MODE>
__global__ __launch_bounds__(256) void mma_gemm(float* __restrict__ C) {
    const __nv_bfloat16* Ahi;
    const __nv_bfloat16* Alo;
    const __nv_bfloat16* Bhi;
    const __nv_bfloat16* Blo;
    if (MODE == 1) {
        Ahi = &g_xhi[0];
        Alo = &g_xlo[0];
        Bhi = &g_wqhi[0];
        Blo = &g_wqlo[0];
    } else {
        Ahi = &g_zhi[0];
        Alo = &g_zlo[0];
        Bhi = &g_wohi[0];
        Blo = &g_wolo[0];
    }

    __shared__ __align__(16) __nv_bfloat16 Ah[128][40];
    __shared__ __align__(16) __nv_bfloat16 Al[128][40];
    __shared__ __align__(16) __nv_bfloat16 Bh[32][136];
    __shared__ __align__(16) __nv_bfloat16 Bl[32][136];

    const int tid = threadIdx.x;
    const int lane = tid & 31;
    const int wid = tid >> 5;
    const int warp_m = wid >> 2;
    const int warp_n = wid & 3;
    const int m0 = blockIdx.y * 128;
    const int n0 = blockIdx.x * 128;

    float acc[4][4][4];
#pragma unroll
    for (int i = 0; i < 4; i++) {
#pragma unroll
        for (int j = 0; j < 4; j++) {
#pragma unroll
            for (int e = 0; e < 4; e++) {
                acc[i][j][e] = 0.f;
            }
        }
    }

    const int a_r = lane & 15;
    const int a_c = ((lane & 16) != 0) ? 8 : 0;
    const int b_r = lane & 15;

    for (int k0 = 0; k0 < 1024; k0 += 32) {
        __syncthreads();
#pragma unroll
        for (int i = 0; i < 2; i++) {
            int idx = tid + i * 256;
            int rr = idx >> 2;
            int cc = (idx & 3) * 8;
            *(uint4*)(&Ah[rr][cc]) = *(const uint4*)(&Ahi[(size_t)(m0 + rr) * 1024 + k0 + cc]);
            *(uint4*)(&Al[rr][cc]) = *(const uint4*)(&Alo[(size_t)(m0 + rr) * 1024 + k0 + cc]);
        }
#pragma unroll
        for (int i = 0; i < 2; i++) {
            int idx = tid + i * 256;
            int rr = idx >> 4;
            int cc = (idx & 15) * 8;
            *(uint4*)(&Bh[rr][cc]) = *(const uint4*)(&Bhi[(size_t)(k0 + rr) * N + n0 + cc]);
            *(uint4*)(&Bl[rr][cc]) = *(const uint4*)(&Blo[(size_t)(k0 + rr) * N + n0 + cc]);
        }
        __syncthreads();

#pragma unroll
        for (int ks = 0; ks < 2; ks++) {
            unsigned int bh0[4];
            unsigned int bh1[4];
            unsigned int bl0[4];
            unsigned int bl1[4];
#pragma unroll
            for (int nf = 0; nf < 4; nf++) {
                LDSM_X2T(bh0[nf], bh1[nf],
                         smem_u32(&Bh[ks * 16 + b_r][warp_n * 32 + nf * 8]));
                LDSM_X2T(bl0[nf], bl1[nf],
                         smem_u32(&Bl[ks * 16 + b_r][warp_n * 32 + nf * 8]));
            }
#pragma unroll
            for (int mf = 0; mf < 4; mf++) {
                unsigned int ah0;
                unsigned int ah1;
                unsigned int ah2;
                unsigned int ah3;
                unsigned int al0;
                unsigned int al1;
                unsigned int al2;
                unsigned int al3;
                LDSM_X4(ah0, ah1, ah2, ah3,
                        smem_u32(&Ah[warp_m * 64 + mf * 16 + a_r][ks * 16 + a_c]));
                LDSM_X4(al0, al1, al2, al3,
                        smem_u32(&Al[warp_m * 64 + mf * 16 + a_r][ks * 16 + a_c]));
#pragma unroll
                for (int nf = 0; nf < 4; nf++) {
                    MMA_BF16(acc[mf][nf][0], acc[mf][nf][1], acc[mf][nf][2], acc[mf][nf][3],
                             ah0, ah1, ah2, ah3, bh0[nf], bh1[nf]);
                    MMA_BF16(acc[mf][nf][0], acc[mf][nf][1], acc[mf][nf][2], acc[mf][nf][3],
                             ah0, ah1, ah2, ah3, bl0[nf], bl1[nf]);
                    MMA_BF16(acc[mf][nf][0], acc[mf][nf][1], acc[mf][nf][2], acc[mf][nf][3],
                             al0, al1, al2, al3, bh0[nf], bh1[nf]);
                }
            }
        }
    }

    const int gg = lane >> 2;
    const int t2 = (lane & 3) * 2;
#pragma unroll
    for (int mf = 0; mf < 4; mf++) {
#pragma unroll
        for (int nf = 0; nf < 4; nf++) {
#pragma unroll
            for (int e = 0; e < 4; e++) {
                const int row = warp_m * 64 + mf * 16 + gg + ((e >= 2) ? 8 : 0);
                const int col = warp_n * 32 + nf * 8 + t2 + (e & 1);
                const int m = m0 + row;
                const int ecol = n0 + col;
                const float v = acc[mf][nf][e];
                if (MODE == 1) {
                    const int bb = m >> 11;
                    const int ss = m & 2047;
                    const int c3 = ecol >> 10;
                    const int rem = ecol & 1023;
                    const int hh = rem >> 6;
                    const int dd = rem & 63;
                    const size_t di = (size_t)(((bb << 4) + hh) * S_ + ss) * DH_ + dd;
                    if (c3 == 0) {
                        g_q[di] = v;
                    } else if (c3 == 1) {
                        g_k[di] = v;
                    } else {
                        __half hv = __float2half_rn(v);
                        g_vh[di] = hv;
                        g_vl[di] = __float2half_rn(v - __half2float(hv));
                    }
                } else {
                    C[(size_t)m * N + ecol] = v;
                }
            }
        }
    }
}

// ---------------------------------------------------------------------------
// RoPE: reads fp32 g_q/g_k, rotates, writes split-bf16 (q scaled by QSCALE).
// ---------------------------------------------------------------------------
__global__ void rope2_kernel() {
    const int total = B_ * H_ * S_ * 32;
    int idx = blockIdx.x * blockDim.x + threadIdx.x;
    bool isq = true;
    if (idx >= total) {
        isq = false;
        idx -= total;
    }
    const float* src;
    if (isq) {
        src = &g_q[0];
    } else {
        src = &g_k[0];
    }

    const int i = idx & 31;
    const int s = (idx >> 5) & (S_ - 1);
    const int base = (idx >> 5) << 6;

    const float invf = (float)exp(-log(10000.0) * (double)i / 32.0);
    const float ang = (float)s * invf;
    const float cv = cosf(ang);
    const float sv = sinf(ang);

    const float u1 = src[base + i];
    const float u2 = src[base + 32 + i];
    float v1 = u1 * cv - u2 * sv;
    float v2 = u2 * cv + u1 * sv;
    if (isq) {
        v1 *= QSCALE;
        v2 *= QSCALE;
        __nv_bfloat16 h1 = __float2bfloat16(v1);
        __nv_bfloat16 h2 = __float2bfloat16(v2);
        g_qh[base + i] = h1;
        g_ql[base + i] = __float2bfloat16(v1 - __bfloat162float(h1));
        g_qh[base + 32 + i] = h2;
        g_ql[base + 32 + i] = __float2bfloat16(v2 - __bfloat162float(h2));
    } else {
        __nv_bfloat16 h1 = __float2bfloat16(v1);
        __nv_bfloat16 h2 = __float2bfloat16(v2);
        g_kh[base + i] = h1;
        g_kl[base + i] = __float2bfloat16(v1 - __bfloat162float(h1));
        g_kh[base + 32 + i] = h2;
        g_kl[base + 32 + i] = __float2bfloat16(v2 - __bfloat162float(h2));
    }
}

// ---------------------------------------------------------------------------
// Tensor-core causal flash attention.
// 64x64 tiles, 128 threads (4 warps, 16 q-rows each). Q in registers.
// S = QK^T via split-bf16 3-pass mma (exp2 domain, scale folded into Q).
// P via ex2.approx.f16x2 (packed directly as f16 A-fragments).
// O += P V via f16 mma, V split f16 hi/lo (2-pass).
// Writes z as split bf16 to g_zhi/g_zlo, layout [b*S+s][h*64+d].
// ---------------------------------------------------------------------------
__global__ __launch_bounds__(128) void attn_tc() {
    __shared__ __align__(16) __nv_bfloat16 Kh[64][72];
    __shared__ __align__(16) __nv_bfloat16 Kl[64][72];
    __shared__ __align__(16) __half Vh[64][72];
    __shared__ __align__(16) __half Vl[64][72];

    const int tid = threadIdx.x;
    const int lane = tid & 31;
    const int wid = tid >> 5;                       // 0..3
    const int qt = (int)gridDim.x - 1 - (int)blockIdx.x;  // reversed: big blocks first
    const int bh = blockIdx.y;

    const size_t base = (size_t)bh * S_ * DH_;

    // ---- stage Q (hi -> Kh, lo -> Kl), then load A-fragments to registers
    for (int i = tid; i < 64 * 8; i += 128) {
        int rr = i >> 3;
        int cc = (i & 7) * 8;
        *(uint4*)(&Kh[rr][cc]) = *(const uint4*)(&g_qh[base + (size_t)(qt * 64 + rr) * 64 + cc]);
        *(uint4*)(&Kl[rr][cc]) = *(const uint4*)(&g_ql[base + (size_t)(qt * 64 + rr) * 64 + cc]);
    }
    __syncthreads();

    const int a_r = lane & 15;
    const int a_c = ((lane & 16) != 0) ? 8 : 0;
    unsigned int qh[4][4];
    unsigned int ql[4][4];
#pragma unroll
    for (int kc = 0; kc < 4; kc++) {
        LDSM_X4(qh[kc][0], qh[kc][1], qh[kc][2], qh[kc][3],
                smem_u32(&Kh[wid * 16 + a_r][kc * 16 + a_c]));
        LDSM_X4(ql[kc][0], ql[kc][1], ql[kc][2], ql[kc][3],
                smem_u32(&Kl[wid * 16 + a_r][kc * 16 + a_c]));
    }

    float o[8][4];
#pragma unroll
    for (int nf = 0; nf < 8; nf++) {
#pragma unroll
        for (int e = 0; e < 4; e++) {
            o[nf][e] = 0.f;
        }
    }
    float m0r = -1e30f;
    float m1r = -1e30f;
    float l0r = 0.f;
    float l1r = 0.f;

    const int b_row = lane & 7;
    const int b_sel = ((lane >> 3) & 1) * 8;

    for (int kt = 0; kt <= qt; kt++) {
        __syncthreads();
        // stage K hi/lo + V hi/lo tiles
        for (int i = tid; i < 64 * 8; i += 128) {
            int rr = i >> 3;
            int cc = (i & 7) * 8;
            size_t gi = base + (size_t)(kt * 64 + rr) * 64 + cc;
            *(uint4*)(&Kh[rr][cc]) = *(const uint4*)(&g_kh[gi]);
            *(uint4*)(&Kl[rr][cc]) = *(const uint4*)(&g_kl[gi]);
            *(uint4*)(&Vh[rr][cc]) = *(const uint4*)(&g_vh[gi]);
            *(uint4*)(&Vl[rr][cc]) = *(const uint4*)(&g_vl[gi]);
        }
        __syncthreads();

        // S = Q K^T (split bf16, 3-pass)
        float sc[8][4];
#pragma unroll
        for (int nf = 0; nf < 8; nf++) {
#pragma unroll
            for (int e = 0; e < 4; e++) {
                sc[nf][e] = 0.f;
            }
        }
#pragma unroll
        for (int nf = 0; nf < 8; nf++) {
#pragma unroll
            for (int kc = 0; kc < 4; kc++) {
                unsigned int kbh0;
                unsigned int kbh1;
                unsigned int kbl0;
                unsigned int kbl1;
                LDSM_X2(kbh0, kbh1, smem_u32(&Kh[nf * 8 + b_row][kc * 16 + b_sel]));
                LDSM_X2(kbl0, kbl1, smem_u32(&Kl[nf * 8 + b_row][kc * 16 + b_sel]));
                MMA_BF16(sc[nf][0], sc[nf][1], sc[nf][2], sc[nf][3],
                         qh[kc][0], qh[kc][1], qh[kc][2], qh[kc][3], kbh0, kbh1);
                MMA_BF16(sc[nf][0], sc[nf][1], sc[nf][2], sc[nf][3],
                         qh[kc][0], qh[kc][1], qh[kc][2], qh[kc][3], kbl0, kbl1);
                MMA_BF16(sc[nf][0], sc[nf][1], sc[nf][2], sc[nf][3],
                         ql[kc][0], ql[kc][1], ql[kc][2], ql[kc][3], kbh0, kbh1);
            }
        }

        // causal mask on the diagonal tile
        if (kt == qt) {
            const int lr0 = wid * 16 + (lane >> 2);
#pragma unroll
            for (int nf = 0; nf < 8; nf++) {
#pragma unroll
                for (int e = 0; e < 4; e++) {
                    const int lr = lr0 + ((e >= 2) ? 8 : 0);
                    const int lc = nf * 8 + (lane & 3) * 2 + (e & 1);
                    if (lc > lr) {
                        sc[nf][e] = -1e30f;
                    }
                }
            }
        }

        // row maxima (two rows per lane), reduce across the 4 lanes of the quad
        float tm0 = -1e30f;
        float tm1 = -1e30f;
#pragma unroll
        for (int nf = 0; nf < 8; nf++) {
            tm0 = fmaxf(tm0, fmaxf(sc[nf][0], sc[nf][1]));
            tm1 = fmaxf(tm1, fmaxf(sc[nf][2], sc[nf][3]));
        }
        tm0 = fmaxf(tm0, __shfl_xor_sync(0xffffffffu, tm0, 1));
        tm0 = fmaxf(tm0, __shfl_xor_sync(0xffffffffu, tm0, 2));
        tm1 = fmaxf(tm1, __shfl_xor_sync(0xffffffffu, tm1, 1));
        tm1 = fmaxf(tm1, __shfl_xor_sync(0xffffffffu, tm1, 2));

        const float mn0 = fmaxf(m0r, tm0);
        const float mn1 = fmaxf(m1r, tm1);
        const float cr0 = exp2f(m0r - mn0);
        const float cr1 = exp2f(m1r - mn1);
        m0r = mn0;
        m1r = mn1;

        // P = exp2(S - m) as packed f16x2 A-fragments; accumulate row sums
        unsigned int pf[4][4];
        float ts0 = 0.f;
        float ts1 = 0.f;
#pragma unroll
        for (int kc = 0; kc < 4; kc++) {
            EX2F16X2(pf[kc][0], sc[2 * kc][0] - mn0, sc[2 * kc][1] - mn0);
            EX2F16X2(pf[kc][1], sc[2 * kc][2] - mn1, sc[2 * kc][3] - mn1);
            EX2F16X2(pf[kc][2], sc[2 * kc + 1][0] - mn0, sc[2 * kc + 1][1] - mn0);
            EX2F16X2(pf[kc][3], sc[2 * kc + 1][2] - mn1, sc[2 * kc + 1][3] - mn1);
#pragma unroll
            for (int e = 0; e < 4; e++) {
                unsigned int u = pf[kc][e];
                __half2 hv = *(__half2*)(&u);
                float2 fv = __half22float2(hv);
                if ((e & 1) == 0) {
                    ts0 += fv.x + fv.y;
                } else {
                    ts1 += fv.x + fv.y;
                }
            }
        }
        ts0 += __shfl_xor_sync(0xffffffffu, ts0, 1);
        ts0 += __shfl_xor_sync(0xffffffffu, ts0, 2);
        ts1 += __shfl_xor_sync(0xffffffffu, ts1, 1);
        ts1 += __shfl_xor_sync(0xffffffffu, ts1, 2);
        l0r = l0r * cr0 + ts0;
        l1r = l1r * cr1 + ts1;

        // rescale O
#pragma unroll
        for (int nf = 0; nf < 8; nf++) {
            o[nf][0] *= cr0;
            o[nf][1] *= cr0;
            o[nf][2] *= cr1;
            o[nf][3] *= cr1;
        }

        // O += P V (f16, 2-pass over V hi/lo)
#pragma unroll
        for (int nf = 0; nf < 8; nf++) {
#pragma unroll
            for (int kc = 0; kc < 4; kc++) {
                unsigned int vb0;
                unsigned int vb1;
                unsigned int wb0;
                unsigned int wb1;
                LDSM_X2T(vb0, vb1, smem_u32(&Vh[kc * 16 + a_r][nf * 8]));
                LDSM_X2T(wb0, wb1, smem_u32(&Vl[kc * 16 + a_r][nf * 8]));
                MMA_F16(o[nf][0], o[nf][1], o[nf][2], o[nf][3],
                        pf[kc][0], pf[kc][1], pf[kc][2], pf[kc][3], vb0, vb1);
                MMA_F16(o[nf][0], o[nf][1], o[nf][2], o[nf][3],
                        pf[kc][0], pf[kc][1], pf[kc][2], pf[kc][3], wb0, wb1);
            }
        }
    }

    // normalize and write z as split bf16
    const float inv0 = 1.f / l0r;
    const float inv1 = 1.f / l1r;
    const int bb = bh >> 4;
    const int hh = bh & 15;
    const int row0 = qt * 64 + wid * 16 + (lane >> 2);
    const int col0 = (lane & 3) * 2;
#pragma unroll
    for (int nf = 0; nf < 8; nf++) {
        const float z00 = o[nf][0] * inv0;
        const float z01 = o[nf][1] * inv0;
        const float z10 = o[nf][2] * inv1;
        const float z11 = o[nf][3] * inv1;
        const size_t i0 = (size_t)(bb * S_ + row0) * D_ + hh * 64 + nf * 8 + col0;
        const size_t i1 = (size_t)(bb * S_ + row0 + 8) * D_ + hh * 64 + nf * 8 + col0;
        __nv_bfloat16 h00 = __float2bfloat16(z00);
        __nv_bfloat16 h01 = __float2bfloat16(z01);
        __nv_bfloat16 h10 = __float2bfloat16(z10);
        __nv_bfloat16 h11 = __float2bfloat16(z11);
        g_zhi[i0] = h00;
        g_zhi[i0 + 1] = h01;
        g_zhi[i1] = h10;
        g_zhi[i1 + 1] = h11;
        g_zlo[i0] = __float2bfloat16(z00 - __bfloat162float(h00));
        g_zlo[i0 + 1] = __float2bfloat16(z01 - __bfloat162float(h01));
        g_zlo[i1] = __float2bfloat16(z10 - __bfloat162float(h10));
        g_zlo[i1 + 1] = __float2bfloat16(z11 - __bfloat162float(h11));
    }
}

// ---------------------------------------------------------------------------
extern "C" void kernel_launch(void* const* d_in, const int* in_sizes, int n_in,
                              void* d_out, int out_size) {
    const float* x = 0;
    const float* W_qkv = 0;
    const float* W_o = 0;

    bool elem_mode = false;
    bool byte_mode = false;
    for (int i = 0; i < n_in; i++) {
        if (in_sizes[i] == 3145728)  elem_mode = true;
        if (in_sizes[i] == 12582912) byte_mode = true;
    }
    if (elem_mode) {
        for (int i = 0; i < n_in; i++) {
            if (in_sizes[i] == 4194304)      x     = (const float*)d_in[i];
            else if (in_sizes[i] == 3145728) W_qkv = (const float*)d_in[i];
            else if (in_sizes[i] == 1048576) W_o   = (const float*)d_in[i];
        }
    } else if (byte_mode) {
        for (int i = 0; i < n_in; i++) {
            if (in_sizes[i] == 16777216)      x     = (const float*)d_in[i];
            else if (in_sizes[i] == 12582912) W_qkv = (const float*)d_in[i];
            else if (in_sizes[i] == 4194304)  W_o   = (const float*)d_in[i];
        }
    }
    if (x == 0 || W_qkv == 0 || W_o == 0) {
        x     = (const float*)d_in[0];
        W_qkv = (const float*)d_in[1];
        W_o   = (const float*)d_in[2];
    }
    float* out = (float*)d_out;

    // 0) split inputs to bf16 hi/lo
    split_kernel<0><<<(M_ROWS * D_ + 255) / 256, 256>>>(x, M_ROWS * D_);
    split_kernel<1><<<(D_ * 3 * D_ + 255) / 256, 256>>>(W_qkv, D_ * 3 * D_);
    split_kernel<2><<<(D_ * D_ + 255) / 256, 256>>>(W_o, D_ * D_);

    // 1) QKV projection (tensor cores): q,k fp32; v split f16
    mma_gemm<3072, 1><<<dim3(3072 / 128, M_ROWS / 128), 256>>>(0);

    // 2) RoPE + split/scale q,k
    rope2_kernel<<<(2 * B_ * H_ * S_ * 32) / 256, 256>>>();

    // 3) Tensor-core causal flash attention -> g_zhi/g_zlo
    attn_tc<<<dim3(S_ / 64, B_ * H_), 128>>>();

    // 4) O-projection (tensor cores)
    mma_gemm<1024, 0><<<dim3(1024 / 128, M_ROWS / 128), 256>>>(out);
}

// round 10
// speedup vs baseline: 2.5214x; 1.1732x over previous
#include <cuda_runtime.h>
#include <cuda_bf16.h>
#include <cuda_fp16.h>
#include <stdint.h>
#include <math.h>

// Problem constants
#define B_  2
#define S_  2048
#define D_  1024
#define H_  16
#define DH_ 64
#define M_ROWS (B_ * S_)

// 0.125 * log2(e)
#define QSCALE 0.18033688011112042f

// ---------------------------------------------------------------------------
// Device-global scratch (allocation-free). Referenced ONLY from device code.
// ---------------------------------------------------------------------------
__device__ __align__(16) float g_q[B_ * H_ * S_ * DH_];
__device__ __align__(16) float g_k[B_ * H_ * S_ * DH_];

__device__ __align__(16) __nv_bfloat16 g_qh[B_ * H_ * S_ * DH_];
__device__ __align__(16) __nv_bfloat16 g_ql[B_ * H_ * S_ * DH_];
__device__ __align__(16) __nv_bfloat16 g_kh[B_ * H_ * S_ * DH_];
__device__ __align__(16) __nv_bfloat16 g_kl[B_ * H_ * S_ * DH_];
__device__ __align__(16) __half        g_vh[B_ * H_ * S_ * DH_];
__device__ __align__(16) __half        g_vl[B_ * H_ * S_ * DH_];

__device__ __align__(16) __nv_bfloat16 g_xhi[M_ROWS * D_];
__device__ __align__(16) __nv_bfloat16 g_xlo[M_ROWS * D_];
__device__ __align__(16) __nv_bfloat16 g_wqhi[D_ * 3 * D_];
__device__ __align__(16) __nv_bfloat16 g_wqlo[D_ * 3 * D_];
__device__ __align__(16) __nv_bfloat16 g_wohi[D_ * D_];
__device__ __align__(16) __nv_bfloat16 g_wolo[D_ * D_];
__device__ __align__(16) __nv_bfloat16 g_zhi[M_ROWS * D_];
__device__ __align__(16) __nv_bfloat16 g_zlo[M_ROWS * D_];

// ---------------------------------------------------------------------------
// PTX helpers (render-safe operand lists)
// ---------------------------------------------------------------------------
__device__ __forceinline__ unsigned int smem_u32(const void* p) {
    unsigned int addr;
    asm("{ .reg .u64 tmp; cvta.to.shared.u64 tmp, %1; cvt.u32.u64 %0, tmp; }"
        : "=r"(addr) : "l"(p));
    return addr;
}

#define LDSM_X4(R0, R1, R2, R3, ADDR)                                         \
    asm volatile(                                                             \
        "ldmatrix.sync.aligned.m8n8.x4.shared.b16 { %0, %1, %2, %3 }, [ %4 ];"\
        : "=r"(R0), "=r"(R1), "=r"(R2), "=r"(R3)                              \
        : "r"(ADDR))

#define LDSM_X2(R0, R1, ADDR)                                                 \
    asm volatile(                                                             \
        "ldmatrix.sync.aligned.m8n8.x2.shared.b16 { %0, %1 }, [ %2 ];"        \
        : "=r"(R0), "=r"(R1)                                                  \
        : "r"(ADDR))

#define LDSM_X2T(R0, R1, ADDR)                                                \
    asm volatile(                                                             \
        "ldmatrix.sync.aligned.m8n8.x2.trans.shared.b16 { %0, %1 }, [ %2 ];"  \
        : "=r"(R0), "=r"(R1)                                                  \
        : "r"(ADDR))

#define MMA_BF16(C0, C1, C2, C3, A0, A1, A2, A3, B0, B1)                      \
    asm volatile(                                                             \
        "mma.sync.aligned.m16n8k16.row.col.f32.bf16.bf16.f32 "                \
        "{ %0, %1, %2, %3 }, { %4, %5, %6, %7 }, { %8, %9 }, "                \
        "{ %0, %1, %2, %3 };"                                                 \
        : "+f"(C0), "+f"(C1), "+f"(C2), "+f"(C3)                              \
        : "r"(A0), "r"(A1), "r"(A2), "r"(A3), "r"(B0), "r"(B1))

#define MMA_F16(C0, C1, C2, C3, A0, A1, A2, A3, B0, B1)                       \
    asm volatile(                                                             \
        "mma.sync.aligned.m16n8k16.row.col.f32.f16.f16.f32 "                  \
        "{ %0, %1, %2, %3 }, { %4, %5, %6, %7 }, { %8, %9 }, "                \
        "{ %0, %1, %2, %3 };"                                                 \
        : "+f"(C0), "+f"(C1), "+f"(C2), "+f"(C3)                              \
        : "r"(A0), "r"(A1), "r"(A2), "r"(A3), "r"(B0), "r"(B1))

#define EX2F16X2(R, S0, S1)                                                   \
    do {                                                                      \
        unsigned int _t;                                                      \
        asm("cvt.rn.f16x2.f32 %0, %1, %2;" : "=r"(_t) : "f"(S1), "f"(S0));    \
        asm("ex2.approx.f16x2 %0, %1;" : "=r"(R) : "r"(_t));                  \
    } while (0)

#define CP_A16(DST, SRC)                                                      \
    asm volatile("cp.async.ca.shared.global [ %0 ], [ %1 ], 16;"              \
                 :: "r"(DST), "l"(SRC))
#define CP_COMMIT() asm volatile("cp.async.commit_group;" ::: "memory")
#define CP_WAIT0()  asm volatile("cp.async.wait_group 0;" ::: "memory")
#define CP_WAIT1()  asm volatile("cp.async.wait_group 1;" ::: "memory")

// ---------------------------------------------------------------------------
// Split fp32 -> (bf16 hi, bf16 lo). WHICH: 0 = x, 1 = W_qkv, 2 = W_o.
// ---------------------------------------------------------------------------
template <int WHICH>
__global__ void split_kernel(const float* src, int n) {
    int i = blockIdx.x * blockDim.x + threadIdx.x;
    if (i >= n) return;
    float v = src[i];
    __nv_bfloat16 hv = __float2bfloat16(v);
    __nv_bfloat16 lv = __float2bfloat16(v - __bfloat162float(hv));
    if (WHICH == 0) { g_xhi[i] = hv; g_xlo[i] = lv; }
    if (WHICH == 1) { g_wqhi[i] = hv; g_wqlo[i] = lv; }
    if (WHICH == 2) { g_wohi[i] = hv; g_wolo[i] = lv; }
}

// ---------------------------------------------------------------------------
// GEMM stage constants (elements)
// ---------------------------------------------------------------------------
#define GA_ELEMS (128 * 40)     // 5120
#define GB_ELEMS (32 * 136)     // 4352
#define GSTAGE_ELEMS (2 * GA_ELEMS + 2 * GB_ELEMS)  // 18944 elems = 37888 B
#define GEMM_SMEM_BYTES (2 * GSTAGE_ELEMS * 2)      // 75776

__device__ __forceinline__ void gemm_stage_load(
    __nv_bfloat16* Ah, __nv_bfloat16* Al,
    __nv_bfloat16* Bh, __nv_bfloat16* Bl,
    const __nv_bfloat16* Ahi, const __nv_bfloat16* Alo,
    const __nv_bfloat16* Bhi, const __nv_bfloat16* Blo,
    int tid, int m0, int n0, int k0, int N) {
#pragma unroll
    for (int i = 0; i < 2; i++) {
        int idx = tid + i * 256;
        int rr = idx >> 2;
        int cc = (idx & 3) * 8;
        CP_A16(smem_u32(&Ah[rr * 40 + cc]), &Ahi[(size_t)(m0 + rr) * 1024 + k0 + cc]);
        CP_A16(smem_u32(&Al[rr * 40 + cc]), &Alo[(size_t)(m0 + rr) * 1024 + k0 + cc]);
    }
#pragma unroll
    for (int i = 0; i < 2; i++) {
        int idx = tid + i * 256;
        int rr = idx >> 4;
        int cc = (idx & 15) * 8;
        CP_A16(smem_u32(&Bh[rr * 136 + cc]), &Bhi[(size_t)(k0 + rr) * N + n0 + cc]);
        CP_A16(smem_u32(&Bl[rr * 136 + cc]), &Blo[(size_t)(k0 + rr) * N + n0 + cc]);
    }
}

// ---------------------------------------------------------------------------
// Split-bf16 tensor-core GEMM, cp.async 2-stage pipelined.
// MODE 1: A = x hi/lo, B = W_qkv hi/lo; epilogue: q,k fp32; v f16 hi/lo.
// MODE 0: A = z hi/lo, B = W_o hi/lo, plain store into C.
// ---------------------------------------------------------------------------
template <int N, int MODE>
__global__ __launch_bounds__(256) void mma_gemm(float* __restrict__ C) {
    extern __shared__ __align__(16) char dynsmem[];
    __nv_bfloat16* sbase = (__nv_bfloat16*)dynsmem;

    const __nv_bfloat16* Ahi;
    const __nv_bfloat16* Alo;
    const __nv_bfloat16* Bhi;
    const __nv_bfloat16* Blo;
    if (MODE == 1) {
        Ahi = &g_xhi[0];
        Alo = &g_xlo[0];
        Bhi = &g_wqhi[0];
        Blo = &g_wqlo[0];
    } else {
        Ahi = &g_zhi[0];
        Alo = &g_zlo[0];
        Bhi = &g_wohi[0];
        Blo = &g_wolo[0];
    }

    const int tid = threadIdx.x;
    const int lane = tid & 31;
    const int wid = tid >> 5;
    const int warp_m = wid >> 2;
    const int warp_n = wid & 3;
    const int m0 = blockIdx.y * 128;
    const int n0 = blockIdx.x * 128;

    float acc[4][4][4];
#pragma unroll
    for (int i = 0; i < 4; i++) {
#pragma unroll
        for (int j = 0; j < 4; j++) {
#pragma unroll
            for (int e = 0; e < 4; e++) {
                acc[i][j][e] = 0.f;
            }
        }
    }

    const int a_r = lane & 15;
    const int a_c = ((lane & 16) != 0) ? 8 : 0;
    const int b_r = lane & 15;
    const int NK = 1024 / 32;

    // Prologue: stage 0
    {
        __nv_bfloat16* Ah = sbase;
        __nv_bfloat16* Al = Ah + GA_ELEMS;
        __nv_bfloat16* Bh = Al + GA_ELEMS;
        __nv_bfloat16* Bl = Bh + GB_ELEMS;
        gemm_stage_load(Ah, Al, Bh, Bl, Ahi, Alo, Bhi, Blo, tid, m0, n0, 0, N);
        CP_COMMIT();
    }

    for (int kt = 0; kt < NK; kt++) {
        if (kt + 1 < NK) {
            __nv_bfloat16* Ah = sbase + ((kt + 1) & 1) * GSTAGE_ELEMS;
            __nv_bfloat16* Al = Ah + GA_ELEMS;
            __nv_bfloat16* Bh = Al + GA_ELEMS;
            __nv_bfloat16* Bl = Bh + GB_ELEMS;
            gemm_stage_load(Ah, Al, Bh, Bl, Ahi, Alo, Bhi, Blo,
                            tid, m0, n0, (kt + 1) * 32, N);
            CP_COMMIT();
            CP_WAIT1();
        } else {
            CP_WAIT0();
        }
        __syncthreads();

        __nv_bfloat16* Ah = sbase + (kt & 1) * GSTAGE_ELEMS;
        __nv_bfloat16* Al = Ah + GA_ELEMS;
        __nv_bfloat16* Bh = Al + GA_ELEMS;
        __nv_bfloat16* Bl = Bh + GB_ELEMS;

#pragma unroll
        for (int ks = 0; ks < 2; ks++) {
            unsigned int bh0[4];
            unsigned int bh1[4];
            unsigned int bl0[4];
            unsigned int bl1[4];
#pragma unroll
            for (int nf = 0; nf < 4; nf++) {
                LDSM_X2T(bh0[nf], bh1[nf],
                         smem_u32(&Bh[(ks * 16 + b_r) * 136 + warp_n * 32 + nf * 8]));
                LDSM_X2T(bl0[nf], bl1[nf],
                         smem_u32(&Bl[(ks * 16 + b_r) * 136 + warp_n * 32 + nf * 8]));
            }
#pragma unroll
            for (int mf = 0; mf < 4; mf++) {
                unsigned int ah0;
                unsigned int ah1;
                unsigned int ah2;
                unsigned int ah3;
                unsigned int al0;
                unsigned int al1;
                unsigned int al2;
                unsigned int al3;
                LDSM_X4(ah0, ah1, ah2, ah3,
                        smem_u32(&Ah[(warp_m * 64 + mf * 16 + a_r) * 40 + ks * 16 + a_c]));
                LDSM_X4(al0, al1, al2, al3,
                        smem_u32(&Al[(warp_m * 64 + mf * 16 + a_r) * 40 + ks * 16 + a_c]));
#pragma unroll
                for (int nf = 0; nf < 4; nf++) {
                    MMA_BF16(acc[mf][nf][0], acc[mf][nf][1], acc[mf][nf][2], acc[mf][nf][3],
                             ah0, ah1, ah2, ah3, bh0[nf], bh1[nf]);
                    MMA_BF16(acc[mf][nf][0], acc[mf][nf][1], acc[mf][nf][2], acc[mf][nf][3],
                             ah0, ah1, ah2, ah3, bl0[nf], bl1[nf]);
                    MMA_BF16(acc[mf][nf][0], acc[mf][nf][1], acc[mf][nf][2], acc[mf][nf][3],
                             al0, al1, al2, al3, bh0[nf], bh1[nf]);
                }
            }
        }
        __syncthreads();
    }

    const int gg = lane >> 2;
    const int t2 = (lane & 3) * 2;
#pragma unroll
    for (int mf = 0; mf < 4; mf++) {
#pragma unroll
        for (int nf = 0; nf < 4; nf++) {
#pragma unroll
            for (int e = 0; e < 4; e++) {
                const int row = warp_m * 64 + mf * 16 + gg + ((e >= 2) ? 8 : 0);
                const int col = warp_n * 32 + nf * 8 + t2 + (e & 1);
                const int m = m0 + row;
                const int ecol = n0 + col;
                const float v = acc[mf][nf][e];
                if (MODE == 1) {
                    const int bb = m >> 11;
                    const int ss = m & 2047;
                    const int c3 = ecol >> 10;
                    const int rem = ecol & 1023;
                    const int hh = rem >> 6;
                    const int dd = rem & 63;
                    const size_t di = (size_t)(((bb << 4) + hh) * S_ + ss) * DH_ + dd;
                    if (c3 == 0) {
                        g_q[di] = v;
                    } else if (c3 == 1) {
                        g_k[di] = v;
                    } else {
                        __half hv = __float2half_rn(v);
                        g_vh[di] = hv;
                        g_vl[di] = __float2half_rn(v - __half2float(hv));
                    }
                } else {
                    C[(size_t)m * N + ecol] = v;
                }
            }
        }
    }
}

// ---------------------------------------------------------------------------
// RoPE: reads fp32 g_q/g_k, rotates, writes split-bf16 (q scaled by QSCALE).
// ---------------------------------------------------------------------------
__global__ void rope2_kernel() {
    const int total = B_ * H_ * S_ * 32;
    int idx = blockIdx.x * blockDim.x + threadIdx.x;
    bool isq = true;
    if (idx >= total) {
        isq = false;
        idx -= total;
    }
    const float* src;
    if (isq) {
        src = &g_q[0];
    } else {
        src = &g_k[0];
    }

    const int i = idx & 31;
    const int s = (idx >> 5) & (S_ - 1);
    const int base = (idx >> 5) << 6;

    const float invf = (float)exp(-log(10000.0) * (double)i / 32.0);
    const float ang = (float)s * invf;
    const float cv = cosf(ang);
    const float sv = sinf(ang);

    const float u1 = src[base + i];
    const float u2 = src[base + 32 + i];
    float v1 = u1 * cv - u2 * sv;
    float v2 = u2 * cv + u1 * sv;
    if (isq) {
        v1 *= QSCALE;
        v2 *= QSCALE;
        __nv_bfloat16 h1 = __float2bfloat16(v1);
        __nv_bfloat16 h2 = __float2bfloat16(v2);
        g_qh[base + i] = h1;
        g_ql[base + i] = __float2bfloat16(v1 - __bfloat162float(h1));
        g_qh[base + 32 + i] = h2;
        g_ql[base + 32 + i] = __float2bfloat16(v2 - __bfloat162float(h2));
    } else {
        __nv_bfloat16 h1 = __float2bfloat16(v1);
        __nv_bfloat16 h2 = __float2bfloat16(v2);
        g_kh[base + i] = h1;
        g_kl[base + i] = __float2bfloat16(v1 - __bfloat162float(h1));
        g_kh[base + 32 + i] = h2;
        g_kl[base + 32 + i] = __float2bfloat16(v2 - __bfloat162float(h2));
    }
}

// ---------------------------------------------------------------------------
// Attention stage constants (elements per 64x72 tile)
// ---------------------------------------------------------------------------
#define ATT_TILE 4608                      // 64*72
#define ATT_STAGE_ELEMS (4 * ATT_TILE)     // Kh,Kl,Vh,Vl = 18432 elems = 36864 B
#define ATTN_SMEM_BYTES (2 * ATT_STAGE_ELEMS * 2)  // 73728

__device__ __forceinline__ void attn_stage_load(
    __nv_bfloat16* Kh, __nv_bfloat16* Kl, __half* Vh, __half* Vl,
    size_t base, int kt, int tid) {
    for (int i = tid; i < 512; i += 128) {
        int rr = i >> 3;
        int cc = (i & 7) * 8;
        size_t gi = base + (size_t)(kt * 64 + rr) * 64 + cc;
        CP_A16(smem_u32(&Kh[rr * 72 + cc]), &g_kh[gi]);
        CP_A16(smem_u32(&Kl[rr * 72 + cc]), &g_kl[gi]);
        CP_A16(smem_u32(&Vh[rr * 72 + cc]), &g_vh[gi]);
        CP_A16(smem_u32(&Vl[rr * 72 + cc]), &g_vl[gi]);
    }
}

// ---------------------------------------------------------------------------
// Tensor-core causal flash attention, cp.async 2-stage pipelined.
// ---------------------------------------------------------------------------
__global__ __launch_bounds__(128) void attn_tc() {
    extern __shared__ __align__(16) char dynsmem[];

    const int tid = threadIdx.x;
    const int lane = tid & 31;
    const int wid = tid >> 5;
    const int qt = (int)gridDim.x - 1 - (int)blockIdx.x;
    const int bh = blockIdx.y;

    const size_t base = (size_t)bh * S_ * DH_;

    __nv_bfloat16* Kh0 = (__nv_bfloat16*)dynsmem;
    __nv_bfloat16* Kl0 = Kh0 + ATT_TILE;

    // stage Q into stage-0 Kh/Kl, move to registers
    for (int i = tid; i < 512; i += 128) {
        int rr = i >> 3;
        int cc = (i & 7) * 8;
        *(uint4*)(&Kh0[rr * 72 + cc]) = *(const uint4*)(&g_qh[base + (size_t)(qt * 64 + rr) * 64 + cc]);
        *(uint4*)(&Kl0[rr * 72 + cc]) = *(const uint4*)(&g_ql[base + (size_t)(qt * 64 + rr) * 64 + cc]);
    }
    __syncthreads();

    const int a_r = lane & 15;
    const int a_c = ((lane & 16) != 0) ? 8 : 0;
    unsigned int qh[4][4];
    unsigned int ql[4][4];
#pragma unroll
    for (int kc = 0; kc < 4; kc++) {
        LDSM_X4(qh[kc][0], qh[kc][1], qh[kc][2], qh[kc][3],
                smem_u32(&Kh0[(wid * 16 + a_r) * 72 + kc * 16 + a_c]));
        LDSM_X4(ql[kc][0], ql[kc][1], ql[kc][2], ql[kc][3],
                smem_u32(&Kl0[(wid * 16 + a_r) * 72 + kc * 16 + a_c]));
    }
    __syncthreads();   // all warps have consumed Q before stage-0 overwrite

    float o[8][4];
#pragma unroll
    for (int nf = 0; nf < 8; nf++) {
#pragma unroll
        for (int e = 0; e < 4; e++) {
            o[nf][e] = 0.f;
        }
    }
    float m0r = -1e30f;
    float m1r = -1e30f;
    float l0r = 0.f;
    float l1r = 0.f;

    const int b_row = lane & 7;
    const int b_sel = ((lane >> 3) & 1) * 8;

    // prologue: issue kt=0 into stage 0
    {
        __nv_bfloat16* Kh = (__nv_bfloat16*)dynsmem;
        __nv_bfloat16* Kl = Kh + ATT_TILE;
        __half* Vh = (__half*)(Kl + ATT_TILE);
        __half* Vl = Vh + ATT_TILE;
        attn_stage_load(Kh, Kl, Vh, Vl, base, 0, tid);
        CP_COMMIT();
    }

    for (int kt = 0; kt <= qt; kt++) {
        if (kt < qt) {
            char* sb = dynsmem + ((kt + 1) & 1) * (ATT_STAGE_ELEMS * 2);
            __nv_bfloat16* Kh = (__nv_bfloat16*)sb;
            __nv_bfloat16* Kl = Kh + ATT_TILE;
            __half* Vh = (__half*)(Kl + ATT_TILE);
            __half* Vl = Vh + ATT_TILE;
            attn_stage_load(Kh, Kl, Vh, Vl, base, kt + 1, tid);
            CP_COMMIT();
            CP_WAIT1();
        } else {
            CP_WAIT0();
        }
        __syncthreads();

        char* sb = dynsmem + (kt & 1) * (ATT_STAGE_ELEMS * 2);
        __nv_bfloat16* Kh = (__nv_bfloat16*)sb;
        __nv_bfloat16* Kl = Kh + ATT_TILE;
        __half* Vh = (__half*)(Kl + ATT_TILE);
        __half* Vl = Vh + ATT_TILE;

        // S = Q K^T (split bf16, 3-pass)
        float sc[8][4];
#pragma unroll
        for (int nf = 0; nf < 8; nf++) {
#pragma unroll
            for (int e = 0; e < 4; e++) {
                sc[nf][e] = 0.f;
            }
        }
#pragma unroll
        for (int nf = 0; nf < 8; nf++) {
#pragma unroll
            for (int kc = 0; kc < 4; kc++) {
                unsigned int kbh0;
                unsigned int kbh1;
                unsigned int kbl0;
                unsigned int kbl1;
                LDSM_X2(kbh0, kbh1, smem_u32(&Kh[(nf * 8 + b_row) * 72 + kc * 16 + b_sel]));
                LDSM_X2(kbl0, kbl1, smem_u32(&Kl[(nf * 8 + b_row) * 72 + kc * 16 + b_sel]));
                MMA_BF16(sc[nf][0], sc[nf][1], sc[nf][2], sc[nf][3],
                         qh[kc][0], qh[kc][1], qh[kc][2], qh[kc][3], kbh0, kbh1);
                MMA_BF16(sc[nf][0], sc[nf][1], sc[nf][2], sc[nf][3],
                         qh[kc][0], qh[kc][1], qh[kc][2], qh[kc][3], kbl0, kbl1);
                MMA_BF16(sc[nf][0], sc[nf][1], sc[nf][2], sc[nf][3],
                         ql[kc][0], ql[kc][1], ql[kc][2], ql[kc][3], kbh0, kbh1);
            }
        }

        if (kt == qt) {
            const int lr0 = wid * 16 + (lane >> 2);
#pragma unroll
            for (int nf = 0; nf < 8; nf++) {
#pragma unroll
                for (int e = 0; e < 4; e++) {
                    const int lr = lr0 + ((e >= 2) ? 8 : 0);
                    const int lc = nf * 8 + (lane & 3) * 2 + (e & 1);
                    if (lc > lr) {
                        sc[nf][e] = -1e30f;
                    }
                }
            }
        }

        float tm0 = -1e30f;
        float tm1 = -1e30f;
#pragma unroll
        for (int nf = 0; nf < 8; nf++) {
            tm0 = fmaxf(tm0, fmaxf(sc[nf][0], sc[nf][1]));
            tm1 = fmaxf(tm1, fmaxf(sc[nf][2], sc[nf][3]));
        }
        tm0 = fmaxf(tm0, __shfl_xor_sync(0xffffffffu, tm0, 1));
        tm0 = fmaxf(tm0, __shfl_xor_sync(0xffffffffu, tm0, 2));
        tm1 = fmaxf(tm1, __shfl_xor_sync(0xffffffffu, tm1, 1));
        tm1 = fmaxf(tm1, __shfl_xor_sync(0xffffffffu, tm1, 2));

        const float mn0 = fmaxf(m0r, tm0);
        const float mn1 = fmaxf(m1r, tm1);
        const float cr0 = exp2f(m0r - mn0);
        const float cr1 = exp2f(m1r - mn1);
        m0r = mn0;
        m1r = mn1;

        unsigned int pf[4][4];
        float ts0 = 0.f;
        float ts1 = 0.f;
#pragma unroll
        for (int kc = 0; kc < 4; kc++) {
            EX2F16X2(pf[kc][0], sc[2 * kc][0] - mn0, sc[2 * kc][1] - mn0);
            EX2F16X2(pf[kc][1], sc[2 * kc][2] - mn1, sc[2 * kc][3] - mn1);
            EX2F16X2(pf[kc][2], sc[2 * kc + 1][0] - mn0, sc[2 * kc + 1][1] - mn0);
            EX2F16X2(pf[kc][3], sc[2 * kc + 1][2] - mn1, sc[2 * kc + 1][3] - mn1);
#pragma unroll
            for (int e = 0; e < 4; e++) {
                unsigned int u = pf[kc][e];
                __half2 hv = *(__half2*)(&u);
                float2 fv = __half22float2(hv);
                if ((e & 1) == 0) {
                    ts0 += fv.x + fv.y;
                } else {
                    ts1 += fv.x + fv.y;
                }
            }
        }
        ts0 += __shfl_xor_sync(0xffffffffu, ts0, 1);
        ts0 += __shfl_xor_sync(0xffffffffu, ts0, 2);
        ts1 += __shfl_xor_sync(0xffffffffu, ts1, 1);
        ts1 += __shfl_xor_sync(0xffffffffu, ts1, 2);
        l0r = l0r * cr0 + ts0;
        l1r = l1r * cr1 + ts1;

#pragma unroll
        for (int nf = 0; nf < 8; nf++) {
            o[nf][0] *= cr0;
            o[nf][1] *= cr0;
            o[nf][2] *= cr1;
            o[nf][3] *= cr1;
        }

#pragma unroll
        for (int nf = 0; nf < 8; nf++) {
#pragma unroll
            for (int kc = 0; kc < 4; kc++) {
                unsigned int vb0;
                unsigned int vb1;
                unsigned int wb0;
                unsigned int wb1;
                LDSM_X2T(vb0, vb1, smem_u32(&Vh[(kc * 16 + a_r) * 72 + nf * 8]));
                LDSM_X2T(wb0, wb1, smem_u32(&Vl[(kc * 16 + a_r) * 72 + nf * 8]));
                MMA_F16(o[nf][0], o[nf][1], o[nf][2], o[nf][3],
                        pf[kc][0], pf[kc][1], pf[kc][2], pf[kc][3], vb0, vb1);
                MMA_F16(o[nf][0], o[nf][1], o[nf][2], o[nf][3],
                        pf[kc][0], pf[kc][1], pf[kc][2], pf[kc][3], wb0, wb1);
            }
        }
        __syncthreads();
    }

    const float inv0 = 1.f / l0r;
    const float inv1 = 1.f / l1r;
    const int bb = bh >> 4;
    const int hh = bh & 15;
    const int row0 = qt * 64 + wid * 16 + (lane >> 2);
    const int col0 = (lane & 3) * 2;
#pragma unroll
    for (int nf = 0; nf < 8; nf++) {
        const float z00 = o[nf][0] * inv0;
        const float z01 = o[nf][1] * inv0;
        const float z10 = o[nf][2] * inv1;
        const float z11 = o[nf][3] * inv1;
        const size_t i0 = (size_t)(bb * S_ + row0) * D_ + hh * 64 + nf * 8 + col0;
        const size_t i1 = (size_t)(bb * S_ + row0 + 8) * D_ + hh * 64 + nf * 8 + col0;
        __nv_bfloat16 h00 = __float2bfloat16(z00);
        __nv_bfloat16 h01 = __float2bfloat16(z01);
        __nv_bfloat16 h10 = __float2bfloat16(z10);
        __nv_bfloat16 h11 = __float2bfloat16(z11);
        g_zhi[i0] = h00;
        g_zhi[i0 + 1] = h01;
        g_zhi[i1] = h10;
        g_zhi[i1 + 1] = h11;
        g_zlo[i0] = __float2bfloat16(z00 - __bfloat162float(h00));
        g_zlo[i0 + 1] = __float2bfloat16(z01 - __bfloat162float(h01));
        g_zlo[i1] = __float2bfloat16(z10 - __bfloat162float(h10));
        g_zlo[i1 + 1] = __float2bfloat16(z11 - __bfloat162float(h11));
    }
}

// ---------------------------------------------------------------------------
extern "C" void kernel_launch(void* const* d_in, const int* in_sizes, int n_in,
                              void* d_out, int out_size) {
    const float* x = 0;
    const float* W_qkv = 0;
    const float* W_o = 0;

    bool elem_mode = false;
    bool byte_mode = false;
    for (int i = 0; i < n_in; i++) {
        if (in_sizes[i] == 3145728)  elem_mode = true;
        if (in_sizes[i] == 12582912) byte_mode = true;
    }
    if (elem_mode) {
        for (int i = 0; i < n_in; i++) {
            if (in_sizes[i] == 4194304)      x     = (const float*)d_in[i];
            else if (in_sizes[i] == 3145728) W_qkv = (const float*)d_in[i];
            else if (in_sizes[i] == 1048576) W_o   = (const float*)d_in[i];
        }
    } else if (byte_mode) {
        for (int i = 0; i < n_in; i++) {
            if (in_sizes[i] == 16777216)      x     = (const float*)d_in[i];
            else if (in_sizes[i] == 12582912) W_qkv = (const float*)d_in[i];
            else if (in_sizes[i] == 4194304)  W_o   = (const float*)d_in[i];
        }
    }
    if (x == 0 || W_qkv == 0 || W_o == 0) {
        x     = (const float*)d_in[0];
        W_qkv = (const float*)d_in[1];
        W_o   = (const float*)d_in[2];
    }
    float* out = (float*)d_out;

    // opt-in dynamic smem (idempotent)
    cudaFuncSetAttribute(mma_gemm<3072, 1>,
                         cudaFuncAttributeMaxDynamicSharedMemorySize, GEMM_SMEM_BYTES);
    cudaFuncSetAttribute(mma_gemm<1024, 0>,
                         cudaFuncAttributeMaxDynamicSharedMemorySize, GEMM_SMEM_BYTES);
    cudaFuncSetAttribute(attn_tc,
                         cudaFuncAttributeMaxDynamicSharedMemorySize, ATTN_SMEM_BYTES);

    // 0) split inputs to bf16 hi/lo
    split_kernel<0><<<(M_ROWS * D_ + 255) / 256, 256>>>(x, M_ROWS * D_);
    split_kernel<1><<<(D_ * 3 * D_ + 255) / 256, 256>>>(W_qkv, D_ * 3 * D_);
    split_kernel<2><<<(D_ * D_ + 255) / 256, 256>>>(W_o, D_ * D_);

    // 1) QKV projection (pipelined tensor cores)
    mma_gemm<3072, 1><<<dim3(3072 / 128, M_ROWS / 128), 256, GEMM_SMEM_BYTES>>>(0);

    // 2) RoPE + split/scale q,k
    rope2_kernel<<<(2 * B_ * H_ * S_ * 32) / 256, 256>>>();

    // 3) Pipelined tensor-core causal flash attention
    attn_tc<<<dim3(S_ / 64, B_ * H_), 128, ATTN_SMEM_BYTES>>>();

    // 4) O-projection (pipelined tensor cores)
    mma_gemm<1024, 0><<<dim3(1024 / 128, M_ROWS / 128), 256, GEMM_SMEM_BYTES>>>(out);
}